// round 10
// baseline (speedup 1.0000x reference)
#include <cuda_runtime.h>
#include <cuda_fp16.h>
#include <cstdint>

#define B_    32
#define CIN   256
#define COUT  256
#define Hs    56
#define Ws    56
#define HW    3136
#define Kdim  2304
#define KZERO 128
#define NIMG  36
#define BTILE 32768
#define PADW  57
#define SLAB  3368
#define TPB   25
#define NTILE (B_*TPB)

// ---------------- device scratch ----------------
__device__ float d_s[B_*CIN];
__device__ float d_t[B_*COUT];
__device__ __half d_xh[(size_t)B_*CIN*SLAB];
__device__ __align__(16) __half d_bimg[(size_t)NIMG*256*64];
__device__ unsigned int d_ctr[2];

// ---------------------------------------------------------------------------
// P0: padded fp16 slab (vectorized, border-only zeroing) + abs-mean
// ---------------------------------------------------------------------------
__global__ void prep_x_kernel(const float* __restrict__ x) {
    int bc = blockIdx.x;
    int t = threadIdx.x;
    const float4* xs4 = (const float4*)(x + (size_t)bc * HW);
    size_t sb = (size_t)bc * SLAB;
    if (t < PADW)        d_xh[sb + t] = __float2half(0.f);
    if (t < 2*PADW)      d_xh[sb + 57*PADW + t] = __float2half(0.f);
    if (t < 56)          d_xh[sb + (t+1)*PADW] = __float2half(0.f);
    if (t < 5)           d_xh[sb + 3363 + t] = __float2half(0.f);
    float sum = 0.f;
    for (int j4 = t; j4 < 784; j4 += 256) {     // 14 float4 per row
        float4 v = xs4[j4];
        int hy = j4 / 14;
        int wx = (j4 - hy*14) * 4;
        size_t p = sb + (size_t)(hy+1)*PADW + wx + 1;
        d_xh[p]   = __float2half(v.x);
        d_xh[p+1] = __float2half(v.y);
        d_xh[p+2] = __float2half(v.z);
        d_xh[p+3] = __float2half(v.w);
        sum += fabsf(v.x) + fabsf(v.y) + fabsf(v.z) + fabsf(v.w);
    }
    __shared__ float red[256];
    red[t] = sum;
    __syncthreads();
    for (int s = 128; s > 0; s >>= 1) {
        if (t < s) red[t] += red[t + s];
        __syncthreads();
    }
    if (t == 0) d_s[bc] = red[0] * (1.0f / HW);
}

// ---------------------------------------------------------------------------
// P1: merged gate (blocks 0..31) + pre-swizzled B images (blocks 32..67)
// ---------------------------------------------------------------------------
__global__ void gate_w_kernel(const float* __restrict__ gw,
                              const float* __restrict__ gb,
                              const float* __restrict__ cw) {
    int blk = blockIdx.x;
    int c = threadIdx.x;
    if (blk >= B_) {                 // ---- prep_w part ----
        int img = blk - B_;
        char* dst = (char*)d_bimg + (size_t)img * BTILE;
        const float* wr = cw + (size_t)c * Kdim + img*64;
        for (int kk = 0; kk < 64; kk++) {
            uint32_t off = (uint32_t)(c*128 + kk*2);
            off ^= (off >> 3) & 0x70;
            *(__half*)(dst + off) = __float2half(wr[kk]);
        }
        return;
    }
    // ---- gate part ----
    int b = blk;
    if (b == 0 && c < 2) d_ctr[c] = 0;
    __shared__ float s_sh[CIN];
    __shared__ float g_sh[COUT];
    __shared__ float red[256];

    s_sh[c] = d_s[b*CIN + c];
    __syncthreads();

    const float* wrow = gw + (size_t)c * CIN;
    float acc = gb[c];
    #pragma unroll 8
    for (int j = 0; j < CIN; j++) acc = fmaf(s_sh[j], wrow[j], acc);
    float g = fmaxf(acc, 0.f);
    g_sh[c] = g;
    __syncthreads();

    int rank = 0;
    for (int j = 0; j < COUT; j++) {
        float gj = g_sh[j];
        rank += (gj < g) || (gj == g && j < c);
    }
    float t = (rank < KZERO) ? 0.f : g;

    red[c] = t;
    __syncthreads();
    for (int s = 128; s > 0; s >>= 1) {
        if (c < s) red[c] += red[c + s];
        __syncthreads();
    }
    d_t[b*COUT + c] = t * ((float)COUT / red[0]);
}

// ---------------------------------------------------------------------------
// Main: persistent mma.sync fp16 implicit GEMM, 2 CTAs/SM, atomic tiling.
// Chunk loop unrolled x2; B cp.async + A gathers interleaved into ks blocks.
// ---------------------------------------------------------------------------
#define SM_A    0
#define SM_B    32768
#define SM_KOFF 98304
#define SM_INV  107520
#define SM_ADD  108544
#define SM_TILE 109568
#define SMEM_SZ 109600

__device__ __forceinline__ uint32_t smem_u32(const void* p) {
    uint32_t a;
    asm("{ .reg .u64 t; cvta.to.shared.u64 t, %1; cvt.u32.u64 %0, t; }" : "=r"(a) : "l"(p));
    return a;
}
__device__ __forceinline__ void ldmx4(uint32_t* r, uint32_t addr) {
    asm volatile("ldmatrix.sync.aligned.m8n8.x4.shared.b16 {%0,%1,%2,%3}, [%4];"
        : "=r"(r[0]), "=r"(r[1]), "=r"(r[2]), "=r"(r[3]) : "r"(addr));
}
__device__ __forceinline__ void mma16816(float* c, const uint32_t* a, const uint32_t* b) {
    asm volatile(
        "mma.sync.aligned.m16n8k16.row.col.f32.f16.f16.f32 "
        "{%0,%1,%2,%3}, {%4,%5,%6,%7}, {%8,%9}, {%0,%1,%2,%3};"
        : "+f"(c[0]), "+f"(c[1]), "+f"(c[2]), "+f"(c[3])
        : "r"(a[0]), "r"(a[1]), "r"(a[2]), "r"(a[3]), "r"(b[0]), "r"(b[1]));
}
__device__ __forceinline__ uint32_t sw128(uint32_t off) {
    return off ^ ((off >> 3) & 0x70);
}
__device__ __forceinline__ void cp16(uint32_t saddr, const void* g) {
    asm volatile("cp.async.cg.shared.global [%0], [%1], 16;" :: "r"(saddr), "l"(g) : "memory");
}
#define CP_COMMIT() asm volatile("cp.async.commit_group;" ::: "memory")
#define CP_WAIT2()  asm volatile("cp.async.wait_group 2;" ::: "memory")
#define CP_WAIT0()  asm volatile("cp.async.wait_group 0;" ::: "memory")

__global__ void __launch_bounds__(256, 2)
conv_mma_kernel(const float* __restrict__ gamma, const float* __restrict__ beta,
                const float* __restrict__ mean,  const float* __restrict__ var,
                float* __restrict__ out)
{
    extern __shared__ __align__(1024) char smem[];
    uint32_t* koff_s = (uint32_t*)(smem + SM_KOFF);
    float* inv_s = (float*)(smem + SM_INV);
    float* add_s = (float*)(smem + SM_ADD);
    volatile unsigned int* tile_s = (volatile unsigned int*)(smem + SM_TILE);
    const uint32_t su = smem_u32(smem);

    const int t = threadIdx.x;
    const int lane = t & 31;
    const int wrp = t >> 5;
    const int wm = (wrp & 1) * 64;
    const int wn = (wrp >> 1) * 32;
    const int nh = blockIdx.x & 1;

    for (int k = t; k < Kdim; k += 256) {
        int ci = k / 9, rs = k - ci*9;
        int dh = rs / 3, dw = rs - dh*3;
        koff_s[k] = (uint32_t)(ci*SLAB + dh*PADW + dw);
    }
    {
        float iv = gamma[t] * rsqrtf(var[t] + 1e-5f);
        inv_s[t] = iv;
        add_s[t] = beta[t] - mean[t]*iv;
    }
    __syncthreads();

    const int r = t & 127;
    const int kqb = (t >> 7) * 8;
    uint32_t stA[8];
    #pragma unroll
    for (int q = 0; q < 8; q++)
        stA[q] = sw128((uint32_t)(r*128 + (kqb + q)*8));

    const int a_row = (lane & 15);
    const int a_kb  = (lane & 16) ? 16 : 0;
    const int b_row = ((lane & 16) ? 8 : 0) + (lane & 7);
    const int b_kb  = (lane & 8) ? 16 : 0;

    const char* bsrc = (const char*)d_bimg + (size_t)nh * 16384;

    // ---- B ring prologue: chunks 0,1,2 -> stages 0,1,2 ----
    #pragma unroll
    for (int pc = 0; pc < 3; pc++) {
        const char* src = bsrc + (size_t)pc * BTILE;
        uint32_t dst = su + SM_B + pc*16384;
        #pragma unroll
        for (int q = 0; q < 4; q++)
            cp16(dst + (uint32_t)(q*256 + t)*16, src + (q*256 + t)*16);
        CP_COMMIT();
    }

    for (;;) {
        if (t == 0) *tile_s = atomicAdd(&d_ctr[nh], 1u);
        __syncthreads();
        const unsigned tile = *tile_s;
        if (tile >= NTILE) break;
        const int b    = tile / TPB;
        const int tloc = tile - b*TPB;
        const unsigned short* xbase = (const unsigned short*)d_xh
            + (size_t)b * (CIN*SLAB) + tloc*128 + r;

        // ---- A prologue: chunk 0 -> buf 0 ----
        {
            char* abase = smem + SM_A;
            #pragma unroll
            for (int q = 0; q < 8; q++) {
                uint4 e = *(const uint4*)(koff_s + (kqb + q)*4);
                uint32_t v0 = xbase[e.x];
                uint32_t v1 = xbase[e.y];
                uint32_t v2 = xbase[e.z];
                uint32_t v3 = xbase[e.w];
                *(uint2*)(abase + stA[q]) = make_uint2(v0 | (v1 << 16), v2 | (v3 << 16));
            }
        }
        CP_WAIT2();
        __syncthreads();

        float acc[4][4][4];
        #pragma unroll
        for (int i = 0; i < 4; i++)
            #pragma unroll
            for (int j = 0; j < 4; j++)
                #pragma unroll
                for (int q = 0; q < 4; q++) acc[i][j][q] = 0.f;

        for (int cb = 0; cb < NIMG; cb += 2) {
            #pragma unroll
            for (int sub = 0; sub < 2; sub++) {
                const int c = cb + sub;
                const int buf = sub;
                const bool more = (c + 1 < NIMG);
                int pc = c + 3; if (pc >= NIMG) pc -= NIMG;
                const char* bpf = bsrc + (size_t)pc * BTILE;
                const uint32_t bdst = su + SM_B + (pc & 3)*16384;
                const uint32_t Ab = su + SM_A + buf*16384;
                const uint32_t Bb = su + SM_B + (c & 3)*16384;
                const int k0n = (c + 1)*64;
                uint2 sA[8];

                #pragma unroll
                for (int ks = 0; ks < 4; ks++) {
                    // fragment loads for this k16 step
                    uint32_t af[4][4];
                    #pragma unroll
                    for (int am = 0; am < 4; am++) {
                        uint32_t off = (uint32_t)((wm + am*16 + a_row)*128 + ks*32 + a_kb);
                        ldmx4(af[am], Ab + sw128(off));
                    }
                    uint32_t bf[4][2];
                    #pragma unroll
                    for (int bp = 0; bp < 2; bp++) {
                        uint32_t rr[4];
                        uint32_t off = (uint32_t)((wn + bp*16 + b_row)*128 + ks*32 + b_kb);
                        ldmx4(rr, Bb + sw128(off));
                        bf[2*bp][0] = rr[0]; bf[2*bp][1] = rr[1];
                        bf[2*bp+1][0] = rr[2]; bf[2*bp+1][1] = rr[3];
                    }
                    // interleaved payload: B prefetch in ks0, 2 A-gather groups per ks
                    if (ks == 0) {
                        #pragma unroll
                        for (int q = 0; q < 4; q++)
                            cp16(bdst + (uint32_t)(q*256 + t)*16, bpf + (q*256 + t)*16);
                        CP_COMMIT();
                    }
                    if (more) {
                        #pragma unroll
                        for (int qq = 0; qq < 2; qq++) {
                            int q = ks*2 + qq;
                            uint4 e = *(const uint4*)(koff_s + k0n + (kqb + q)*4);
                            uint32_t v0 = xbase[e.x];
                            uint32_t v1 = xbase[e.y];
                            uint32_t v2 = xbase[e.z];
                            uint32_t v3 = xbase[e.w];
                            sA[q] = make_uint2(v0 | (v1 << 16), v2 | (v3 << 16));
                        }
                    }
                    // 16 MMAs
                    #pragma unroll
                    for (int am = 0; am < 4; am++)
                        #pragma unroll
                        for (int bn = 0; bn < 4; bn++)
                            mma16816(acc[am][bn], af[am], bf[bn]);
                }

                if (more) {
                    char* abase = smem + SM_A + (buf^1)*16384;
                    #pragma unroll
                    for (int q = 0; q < 8; q++)
                        *(uint2*)(abase + stA[q]) = sA[q];
                }
                CP_WAIT2();
                __syncthreads();
            }
        }

        // ---- epilogue: BN + ReLU + gate, predicated NCHW store ----
        const float* tp = d_t + b*COUT;
        #pragma unroll
        for (int am = 0; am < 4; am++) {
            int mr0 = tloc*128 + wm + am*16 + (lane >> 2);
            #pragma unroll
            for (int half = 0; half < 2; half++) {
                int mp = mr0 + half*8;
                int h = mp / PADW;
                int w = mp - h*PADW;
                bool valid = (h < Hs) && (w < Ws);
                float* op = out + (size_t)b*(COUT*HW) + h*Ws + w;
                #pragma unroll
                for (int bn = 0; bn < 4; bn++) {
                    int n = nh*128 + wn + bn*8 + 2*(lane & 3);
                    float v0 = fmaf(acc[am][bn][half*2+0], inv_s[n],   add_s[n]);
                    float v1 = fmaf(acc[am][bn][half*2+1], inv_s[n+1], add_s[n+1]);
                    v0 = fmaxf(v0, 0.f) * __ldg(tp + n);
                    v1 = fmaxf(v1, 0.f) * __ldg(tp + n + 1);
                    if (valid) {
                        op[(size_t)n * HW] = v0;
                        op[(size_t)(n+1) * HW] = v1;
                    }
                }
            }
        }
    }
    CP_WAIT0();
}

// ---------------------------------------------------------------------------
extern "C" void kernel_launch(void* const* d_in, const int* in_sizes, int n_in,
                              void* d_out, int out_size) {
    const float* x     = (const float*)d_in[0];
    const float* cw    = (const float*)d_in[1];
    const float* gw    = (const float*)d_in[2];
    const float* gb    = (const float*)d_in[3];
    const float* gamma = (const float*)d_in[4];
    const float* beta  = (const float*)d_in[5];
    const float* mean  = (const float*)d_in[6];
    const float* var   = (const float*)d_in[7];
    float* out = (float*)d_out;

    static bool attr_set = false;
    if (!attr_set) {
        cudaFuncSetAttribute(conv_mma_kernel,
                             cudaFuncAttributeMaxDynamicSharedMemorySize, SMEM_SZ);
        attr_set = true;
    }

    prep_x_kernel<<<B_*CIN, 256>>>(x);
    gate_w_kernel<<<B_ + NIMG, 256>>>(gw, gb, cw);
    conv_mma_kernel<<<296, 256, SMEM_SZ>>>(gamma, beta, mean, var, out);
}

// round 11
// speedup vs baseline: 1.3937x; 1.3937x over previous
#include <cuda_runtime.h>
#include <cuda_fp16.h>
#include <cstdint>

#define B_    32
#define CIN   256
#define COUT  256
#define Hs    56
#define Ws    56
#define HW    3136
#define Kdim  2304
#define KZERO 128
#define NIMG  36
#define BTILE 32768
#define PADW  57
#define SLAB  3368
#define TPB   25
#define NTILE (B_*TPB)

// ---------------- device scratch ----------------
__device__ float d_s[B_*CIN];
__device__ float d_t[B_*COUT];
__device__ __half d_xh[(size_t)B_*CIN*SLAB];
__device__ __align__(16) __half d_bimg[(size_t)NIMG*256*64];
__device__ unsigned int d_ctr[2];

// ---------------------------------------------------------------------------
// P0: padded fp16 slab (vectorized, border-only zeroing) + abs-mean
// ---------------------------------------------------------------------------
__global__ void prep_x_kernel(const float* __restrict__ x) {
    int bc = blockIdx.x;
    int t = threadIdx.x;
    const float4* xs4 = (const float4*)(x + (size_t)bc * HW);
    size_t sb = (size_t)bc * SLAB;
    if (t < PADW)        d_xh[sb + t] = __float2half(0.f);
    if (t < 2*PADW)      d_xh[sb + 57*PADW + t] = __float2half(0.f);
    if (t < 56)          d_xh[sb + (t+1)*PADW] = __float2half(0.f);
    if (t < 5)           d_xh[sb + 3363 + t] = __float2half(0.f);
    float sum = 0.f;
    for (int j4 = t; j4 < 784; j4 += 256) {     // 14 float4 per row
        float4 v = xs4[j4];
        int hy = j4 / 14;
        int wx = (j4 - hy*14) * 4;
        size_t p = sb + (size_t)(hy+1)*PADW + wx + 1;
        d_xh[p]   = __float2half(v.x);
        d_xh[p+1] = __float2half(v.y);
        d_xh[p+2] = __float2half(v.z);
        d_xh[p+3] = __float2half(v.w);
        sum += fabsf(v.x) + fabsf(v.y) + fabsf(v.z) + fabsf(v.w);
    }
    __shared__ float red[256];
    red[t] = sum;
    __syncthreads();
    for (int s = 128; s > 0; s >>= 1) {
        if (t < s) red[t] += red[t + s];
        __syncthreads();
    }
    if (t == 0) d_s[bc] = red[0] * (1.0f / HW);
}

// ---------------------------------------------------------------------------
// P1: merged gate (blocks 0..31) + pre-swizzled B images (blocks 32..67)
// ---------------------------------------------------------------------------
__global__ void gate_w_kernel(const float* __restrict__ gw,
                              const float* __restrict__ gb,
                              const float* __restrict__ cw) {
    int blk = blockIdx.x;
    int c = threadIdx.x;
    if (blk >= B_) {                 // ---- prep_w part ----
        int img = blk - B_;
        char* dst = (char*)d_bimg + (size_t)img * BTILE;
        const float* wr = cw + (size_t)c * Kdim + img*64;
        for (int kk = 0; kk < 64; kk++) {
            uint32_t off = (uint32_t)(c*128 + kk*2);
            off ^= (off >> 3) & 0x70;
            *(__half*)(dst + off) = __float2half(wr[kk]);
        }
        return;
    }
    // ---- gate part ----
    int b = blk;
    if (b == 0 && c < 2) d_ctr[c] = 0;
    __shared__ float s_sh[CIN];
    __shared__ float g_sh[COUT];
    __shared__ float red[256];

    s_sh[c] = d_s[b*CIN + c];
    __syncthreads();

    const float* wrow = gw + (size_t)c * CIN;
    float acc = gb[c];
    #pragma unroll 8
    for (int j = 0; j < CIN; j++) acc = fmaf(s_sh[j], wrow[j], acc);
    float g = fmaxf(acc, 0.f);
    g_sh[c] = g;
    __syncthreads();

    int rank = 0;
    for (int j = 0; j < COUT; j++) {
        float gj = g_sh[j];
        rank += (gj < g) || (gj == g && j < c);
    }
    float t = (rank < KZERO) ? 0.f : g;

    red[c] = t;
    __syncthreads();
    for (int s = 128; s > 0; s >>= 1) {
        if (c < s) red[c] += red[c + s];
        __syncthreads();
    }
    d_t[b*COUT + c] = t * ((float)COUT / red[0]);
}

// ---------------------------------------------------------------------------
// Main: persistent mma.sync fp16 implicit GEMM, 2 CTAs/SM, atomic tiling.
// (R9 mainloop verbatim — gather burst before compute block, drain after.)
// ---------------------------------------------------------------------------
#define SM_A    0
#define SM_B    32768
#define SM_KOFF 98304
#define SM_INV  107520
#define SM_ADD  108544
#define SM_TILE 109568
#define SMEM_SZ 109600

__device__ __forceinline__ uint32_t smem_u32(const void* p) {
    uint32_t a;
    asm("{ .reg .u64 t; cvta.to.shared.u64 t, %1; cvt.u32.u64 %0, t; }" : "=r"(a) : "l"(p));
    return a;
}
__device__ __forceinline__ void ldmx4(uint32_t* r, uint32_t addr) {
    asm volatile("ldmatrix.sync.aligned.m8n8.x4.shared.b16 {%0,%1,%2,%3}, [%4];"
        : "=r"(r[0]), "=r"(r[1]), "=r"(r[2]), "=r"(r[3]) : "r"(addr));
}
__device__ __forceinline__ void mma16816(float* c, const uint32_t* a, const uint32_t* b) {
    asm volatile(
        "mma.sync.aligned.m16n8k16.row.col.f32.f16.f16.f32 "
        "{%0,%1,%2,%3}, {%4,%5,%6,%7}, {%8,%9}, {%0,%1,%2,%3};"
        : "+f"(c[0]), "+f"(c[1]), "+f"(c[2]), "+f"(c[3])
        : "r"(a[0]), "r"(a[1]), "r"(a[2]), "r"(a[3]), "r"(b[0]), "r"(b[1]));
}
__device__ __forceinline__ uint32_t sw128(uint32_t off) {
    return off ^ ((off >> 3) & 0x70);
}
__device__ __forceinline__ void cp16(uint32_t saddr, const void* g) {
    asm volatile("cp.async.cg.shared.global [%0], [%1], 16;" :: "r"(saddr), "l"(g) : "memory");
}
#define CP_COMMIT() asm volatile("cp.async.commit_group;" ::: "memory")
#define CP_WAIT2()  asm volatile("cp.async.wait_group 2;" ::: "memory")
#define CP_WAIT0()  asm volatile("cp.async.wait_group 0;" ::: "memory")

__global__ void __launch_bounds__(256, 2)
conv_mma_kernel(const float* __restrict__ gamma, const float* __restrict__ beta,
                const float* __restrict__ mean,  const float* __restrict__ var,
                float* __restrict__ out)
{
    extern __shared__ __align__(1024) char smem[];
    uint32_t* koff_s = (uint32_t*)(smem + SM_KOFF);
    float* inv_s = (float*)(smem + SM_INV);
    float* add_s = (float*)(smem + SM_ADD);
    volatile unsigned int* tile_s = (volatile unsigned int*)(smem + SM_TILE);
    const uint32_t su = smem_u32(smem);

    const int t = threadIdx.x;
    const int lane = t & 31;
    const int wrp = t >> 5;
    const int wm = (wrp & 1) * 64;
    const int wn = (wrp >> 1) * 32;
    const int nh = blockIdx.x & 1;

    for (int k = t; k < Kdim; k += 256) {
        int ci = k / 9, rs = k - ci*9;
        int dh = rs / 3, dw = rs - dh*3;
        koff_s[k] = (uint32_t)(ci*SLAB + dh*PADW + dw);
    }
    {
        float iv = gamma[t] * rsqrtf(var[t] + 1e-5f);
        inv_s[t] = iv;
        add_s[t] = beta[t] - mean[t]*iv;
    }
    __syncthreads();

    const int r = t & 127;
    const int kqb = (t >> 7) * 8;      // 0 or 8
    uint32_t stA[8];
    #pragma unroll
    for (int q = 0; q < 8; q++)
        stA[q] = sw128((uint32_t)(r*128 + (kqb + q)*8));

    const int a_row = (lane & 15);
    const int a_kb  = (lane & 16) ? 16 : 0;
    const int b_row = ((lane & 16) ? 8 : 0) + (lane & 7);
    const int b_kb  = (lane & 8) ? 16 : 0;

    const char* bsrc = (const char*)d_bimg + (size_t)nh * 16384;

    // ---- B ring prologue: chunks 0,1,2 into stages 0,1,2 ----
    #pragma unroll
    for (int pc = 0; pc < 3; pc++) {
        const char* src = bsrc + (size_t)pc * BTILE;
        uint32_t dst = su + SM_B + pc*16384;
        #pragma unroll
        for (int q = 0; q < 4; q++)
            cp16(dst + (uint32_t)(q*256 + t)*16, src + (q*256 + t)*16);
        CP_COMMIT();
    }

    for (;;) {
        if (t == 0) *tile_s = atomicAdd(&d_ctr[nh], 1u);
        __syncthreads();
        const unsigned tile = *tile_s;
        if (tile >= NTILE) break;
        const int b    = tile / TPB;
        const int tloc = tile - b*TPB;
        const unsigned short* xbase = (const unsigned short*)d_xh
            + (size_t)b * (CIN*SLAB) + tloc*128 + r;

        // ---- A prologue: chunk 0 -> buf 0 ----
        {
            char* abase = smem + SM_A;
            #pragma unroll
            for (int q = 0; q < 8; q++) {
                uint4 e = *(const uint4*)(koff_s + (kqb + q)*4);
                uint32_t v0 = xbase[e.x];
                uint32_t v1 = xbase[e.y];
                uint32_t v2 = xbase[e.z];
                uint32_t v3 = xbase[e.w];
                *(uint2*)(abase + stA[q]) = make_uint2(v0 | (v1 << 16), v2 | (v3 << 16));
            }
        }
        CP_WAIT2();
        __syncthreads();

        float acc[4][4][4];
        #pragma unroll
        for (int i = 0; i < 4; i++)
            #pragma unroll
            for (int j = 0; j < 4; j++)
                #pragma unroll
                for (int q = 0; q < 4; q++) acc[i][j][q] = 0.f;

        for (int c = 0; c < NIMG; c++) {
            const int buf = c & 1;
            const bool more = (c + 1 < NIMG);

            // B prefetch (c+3) mod 36 — stream continues into next tile
            {
                int pc = c + 3; if (pc >= NIMG) pc -= NIMG;
                const char* src = bsrc + (size_t)pc * BTILE;
                uint32_t dst = su + SM_B + (pc & 3)*16384;
                #pragma unroll
                for (int q = 0; q < 4; q++)
                    cp16(dst + (uint32_t)(q*256 + t)*16, src + (q*256 + t)*16);
            }
            CP_COMMIT();

            uint2 sA[8];
            if (more) {
                const int k0 = (c + 1)*64;
                #pragma unroll
                for (int q = 0; q < 8; q++) {
                    uint4 e = *(const uint4*)(koff_s + k0 + (kqb + q)*4);
                    uint32_t v0 = xbase[e.x];
                    uint32_t v1 = xbase[e.y];
                    uint32_t v2 = xbase[e.z];
                    uint32_t v3 = xbase[e.w];
                    sA[q] = make_uint2(v0 | (v1 << 16), v2 | (v3 << 16));
                }
            }

            const uint32_t Ab = su + SM_A + buf*16384;
            const uint32_t Bb = su + SM_B + (c & 3)*16384;
            #pragma unroll
            for (int ks = 0; ks < 4; ks++) {
                uint32_t af[4][4];
                #pragma unroll
                for (int am = 0; am < 4; am++) {
                    uint32_t off = (uint32_t)((wm + am*16 + a_row)*128 + ks*32 + a_kb);
                    ldmx4(af[am], Ab + sw128(off));
                }
                uint32_t bf[4][2];
                #pragma unroll
                for (int bp = 0; bp < 2; bp++) {
                    uint32_t rr[4];
                    uint32_t off = (uint32_t)((wn + bp*16 + b_row)*128 + ks*32 + b_kb);
                    ldmx4(rr, Bb + sw128(off));
                    bf[2*bp][0] = rr[0]; bf[2*bp][1] = rr[1];
                    bf[2*bp+1][0] = rr[2]; bf[2*bp+1][1] = rr[3];
                }
                #pragma unroll
                for (int am = 0; am < 4; am++)
                    #pragma unroll
                    for (int bn = 0; bn < 4; bn++)
                        mma16816(acc[am][bn], af[am], bf[bn]);
            }

            if (more) {
                char* abase = smem + SM_A + (buf^1)*16384;
                #pragma unroll
                for (int q = 0; q < 8; q++)
                    *(uint2*)(abase + stA[q]) = sA[q];
            }
            CP_WAIT2();
            __syncthreads();
        }

        // ---- epilogue: BN + ReLU + gate, predicated NCHW store ----
        const float* tp = d_t + b*COUT;
        #pragma unroll
        for (int am = 0; am < 4; am++) {
            int mr0 = tloc*128 + wm + am*16 + (lane >> 2);
            #pragma unroll
            for (int half = 0; half < 2; half++) {
                int mp = mr0 + half*8;
                int h = mp / PADW;
                int w = mp - h*PADW;
                bool valid = (h < Hs) && (w < Ws);
                float* op = out + (size_t)b*(COUT*HW) + h*Ws + w;
                #pragma unroll
                for (int bn = 0; bn < 4; bn++) {
                    int n = nh*128 + wn + bn*8 + 2*(lane & 3);
                    float v0 = fmaf(acc[am][bn][half*2+0], inv_s[n],   add_s[n]);
                    float v1 = fmaf(acc[am][bn][half*2+1], inv_s[n+1], add_s[n+1]);
                    v0 = fmaxf(v0, 0.f) * __ldg(tp + n);
                    v1 = fmaxf(v1, 0.f) * __ldg(tp + n + 1);
                    if (valid) {
                        op[(size_t)n * HW] = v0;
                        op[(size_t)(n+1) * HW] = v1;
                    }
                }
            }
        }
    }
    CP_WAIT0();
}

// ---------------------------------------------------------------------------
extern "C" void kernel_launch(void* const* d_in, const int* in_sizes, int n_in,
                              void* d_out, int out_size) {
    const float* x     = (const float*)d_in[0];
    const float* cw    = (const float*)d_in[1];
    const float* gw    = (const float*)d_in[2];
    const float* gb    = (const float*)d_in[3];
    const float* gamma = (const float*)d_in[4];
    const float* beta  = (const float*)d_in[5];
    const float* mean  = (const float*)d_in[6];
    const float* var   = (const float*)d_in[7];
    float* out = (float*)d_out;

    static bool attr_set = false;
    if (!attr_set) {
        cudaFuncSetAttribute(conv_mma_kernel,
                             cudaFuncAttributeMaxDynamicSharedMemorySize, SMEM_SZ);
        attr_set = true;
    }

    prep_x_kernel<<<B_*CIN, 256>>>(x);
    gate_w_kernel<<<B_ + NIMG, 256>>>(gw, gb, cw);
    conv_mma_kernel<<<296, 256, SMEM_SZ>>>(gamma, beta, mean, var, out);
}